// round 2
// baseline (speedup 1.0000x reference)
#include <cuda_runtime.h>
#include <math.h>

#define DD 128
static constexpr int MAXG = 5120;
static constexpr int MAXE = 262144;

__device__ __align__(16) float g_h  [MAXG * DD];
__device__ __align__(16) float g_xl [MAXG * DD];
__device__ __align__(16) float g_xr [MAXG * DD];
__device__ __align__(16) float g_gat[MAXG * DD];
__device__ int   g_src[MAXE];
__device__ int   g_dst[MAXE];
__device__ int   g_es [MAXE];
__device__ int   g_off[MAXG + 1];
__device__ int   g_cur[MAXG];
__device__ int   g_deg[MAXG];
__device__ float g_h1 [DD];
__device__ int   g_flag;

// ---------------------------------------------------------------------------
// K0: zero per-run scratch (graph replays reuse device globals!)
// ---------------------------------------------------------------------------
__global__ void kz(int G) {
    int i = blockIdx.x * blockDim.x + threadIdx.x;
    if (i < G)  g_deg[i] = 0;
    if (i < DD) g_h1[i]  = 0.f;
    if (i == 0) g_flag   = 0;
}

// ---------------------------------------------------------------------------
// K1: detect edge_index dtype. If the buffer is int64 (values < 5000), every
// odd 32-bit word of the first row is 0. If int32, odd words are random edge
// ids -> OR over them is nonzero with overwhelming probability.
// ---------------------------------------------------------------------------
__global__ void kflag(const int* __restrict__ w, int E) {
    int i = blockIdx.x * blockDim.x + threadIdx.x;
    int v = 0;
    if (i < E) v = w[2 * i + 1];
    #pragma unroll
    for (int o = 16; o; o >>= 1) v |= __shfl_xor_sync(0xffffffffu, v, o);
    if ((threadIdx.x & 31) == 0 && v) atomicOr(&g_flag, 1);
}

// ---------------------------------------------------------------------------
// K2: convert edges to int32 src/dst arrays + degree histogram
// ---------------------------------------------------------------------------
__global__ void kconv(const void* __restrict__ eidx, int E) {
    int i = blockIdx.x * blockDim.x + threadIdx.x;
    if (i >= E) return;
    int s, d;
    if (g_flag == 0) {
        const long long* p = (const long long*)eidx;
        s = (int)p[i]; d = (int)p[(size_t)E + i];
    } else {
        const int* p = (const int*)eidx;
        s = p[i]; d = p[E + i];
    }
    g_src[i] = s;
    g_dst[i] = d;
    atomicAdd(&g_deg[d], 1);
}

// ---------------------------------------------------------------------------
// K3: single-block chunked Hillis-Steele exclusive scan over degrees -> CSR
// ---------------------------------------------------------------------------
__global__ void kscan(int G) {
    __shared__ int s[1024];
    __shared__ int base;
    int tid = threadIdx.x;
    if (tid == 0) { base = 0; g_off[0] = 0; }
    __syncthreads();
    for (int start = 0; start < G; start += 1024) {
        int i = start + tid;
        int v = (i < G) ? g_deg[i] : 0;
        s[tid] = v;
        __syncthreads();
        for (int o = 1; o < 1024; o <<= 1) {
            int t = (tid >= o) ? s[tid - o] : 0;
            __syncthreads();
            s[tid] += t;
            __syncthreads();
        }
        if (i < G) {
            g_off[i + 1] = base + s[tid];
            g_cur[i]     = base + s[tid] - v;   // exclusive offset = cursor
        }
        __syncthreads();
        if (tid == 0) base += s[1023];
        __syncthreads();
    }
}

// ---------------------------------------------------------------------------
// K4: scatter edges into CSR buckets (store src per slot)
// ---------------------------------------------------------------------------
__global__ void kscatter(int E) {
    int i = blockIdx.x * blockDim.x + threadIdx.x;
    if (i >= E) return;
    int d   = g_dst[i];
    int pos = atomicAdd(&g_cur[d], 1);
    g_es[pos] = g_src[i];
}

// ---------------------------------------------------------------------------
// K5: h[g,d] = relu(sum_i x[g,i] * W_in[g,i,d] + b_in[g,d])
// one block per gene, 128 threads (=D), streams 32KB of W_in per block
// ---------------------------------------------------------------------------
__global__ void kh(const float* __restrict__ x, const float* __restrict__ Win,
                   const float* __restrict__ bin, int IN) {
    __shared__ float sx[256];
    int g = blockIdx.x, d = threadIdx.x;
    for (int i = d; i < IN; i += DD) sx[i] = x[(size_t)g * IN + i];
    __syncthreads();
    float acc = bin[(size_t)g * DD + d];
    const float* w = Win + (size_t)g * IN * DD + d;
    #pragma unroll 8
    for (int i = 0; i < IN; i++) acc += sx[i] * w[(size_t)i * DD];
    g_h[(size_t)g * DD + d] = fmaxf(acc, 0.f);
}

// ---------------------------------------------------------------------------
// K6: xl = h@W_l + b_l ; xr = h@W_r + b_r   (8-row register tiling)
// ---------------------------------------------------------------------------
__global__ void kxlxr(const float* __restrict__ Wl, const float* __restrict__ bl,
                      const float* __restrict__ Wr, const float* __restrict__ br,
                      int G) {
    __shared__ float sh[8][DD];
    int g0 = blockIdx.x * 8, d = threadIdx.x;
    int nr = min(8, G - g0);
    for (int r = 0; r < nr; r++) sh[r][d] = g_h[(size_t)(g0 + r) * DD + d];
    __syncthreads();
    float al[8], ar[8];
    float bld = bl[d], brd = br[d];
    #pragma unroll
    for (int r = 0; r < 8; r++) { al[r] = bld; ar[r] = brd; }
    for (int k = 0; k < DD; k++) {
        float wl = Wl[k * DD + d];
        float wr = Wr[k * DD + d];
        #pragma unroll
        for (int r = 0; r < 8; r++) {
            float hk = sh[r][k];
            al[r] = fmaf(hk, wl, al[r]);
            ar[r] = fmaf(hk, wr, ar[r]);
        }
    }
    for (int r = 0; r < nr; r++) {
        g_xl[(size_t)(g0 + r) * DD + d] = al[r];
        g_xr[(size_t)(g0 + r) * DD + d] = ar[r];
    }
}

// ---------------------------------------------------------------------------
// K7: GATv2 per destination node. 4 warps/block, each warp runs an online
// softmax over its strided share of edges (warp 0 also handles the implicit
// self loop); register-resident (m, z, acc[4]) per lane; merged via smem.
// ---------------------------------------------------------------------------
__global__ void kgat(const float* __restrict__ att, const float* __restrict__ bias) {
    int n = blockIdx.x;
    int tid = threadIdx.x, lane = tid & 31, wid = tid >> 5;

    const float4* xlv  = (const float4*)g_xl;
    float4 att4 = ((const float4*)att)[lane];
    float4 xr4  = ((const float4*)(g_xr + (size_t)n * DD))[lane];

    int beg = g_off[n], end = g_off[n + 1];
    float  m = -INFINITY, z = 0.f;
    float4 acc = make_float4(0.f, 0.f, 0.f, 0.f);

    int  idx  = beg + wid;
    bool self = (wid == 0);                 // implicit self loop -> warp 0
    while (self || idx < end) {
        int src;
        if (self) { src = n; self = false; }
        else      { src = g_es[idx]; idx += 4; }

        float4 xl4 = xlv[(size_t)src * (DD / 4) + lane];
        float tx = xl4.x + xr4.x, ty = xl4.y + xr4.y;
        float tz = xl4.z + xr4.z, tw = xl4.w + xr4.w;
        tx = tx >= 0.f ? tx : 0.2f * tx;
        ty = ty >= 0.f ? ty : 0.2f * ty;
        tz = tz >= 0.f ? tz : 0.2f * tz;
        tw = tw >= 0.f ? tw : 0.2f * tw;
        float p = att4.x * tx + att4.y * ty + att4.z * tz + att4.w * tw;
        #pragma unroll
        for (int o = 16; o; o >>= 1) p += __shfl_xor_sync(0xffffffffu, p, o);

        float mn = fmaxf(m, p);
        float sc = __expf(m - mn);          // exp(-inf) = 0 on first edge
        float w  = __expf(p - mn);
        z     = z * sc + w;
        acc.x = acc.x * sc + w * xl4.x;
        acc.y = acc.y * sc + w * xl4.y;
        acc.z = acc.z * sc + w * xl4.z;
        acc.w = acc.w * sc + w * xl4.w;
        m = mn;
    }

    __shared__ float sm[4], szz[4];
    __shared__ float sacc[4][DD];
    if (lane == 0) { sm[wid] = m; szz[wid] = z; }
    sacc[wid][lane * 4 + 0] = acc.x;
    sacc[wid][lane * 4 + 1] = acc.y;
    sacc[wid][lane * 4 + 2] = acc.z;
    sacc[wid][lane * 4 + 3] = acc.w;
    __syncthreads();

    int d = tid;
    float M = fmaxf(fmaxf(sm[0], sm[1]), fmaxf(sm[2], sm[3]));
    float Z = 0.f, A = 0.f;
    #pragma unroll
    for (int w2 = 0; w2 < 4; w2++) {
        float s = __expf(sm[w2] - M);       // empty warp: sm=-inf -> s=0
        Z += szz[w2] * s;
        A += sacc[w2][d] * s;
    }
    float o = A / Z + bias[d];
    g_gat[(size_t)n * DD + d] = o >= 0.f ? o : 0.2f * o;
}

// ---------------------------------------------------------------------------
// K8: h1[j] += sum_t flat[t] * W1[t,j]  (dominant 328MB stream)
// 256 threads = 2 row-interleaved groups of 128 (j); 1024 rows per block.
// ---------------------------------------------------------------------------
__global__ void kmlp1(const float* __restrict__ W1, int GD) {
    __shared__ float sf[1024];
    int j    = threadIdx.x & 127;
    int half = threadIdx.x >> 7;
    int base = blockIdx.x * 1024;
    int lim  = min(1024, GD - base);
    for (int i = threadIdx.x; i < lim; i += 256) sf[i] = g_gat[base + i];
    __syncthreads();
    float acc = 0.f;
    #pragma unroll 8
    for (int i = half; i < lim; i += 2)
        acc = fmaf(sf[i], __ldg(&W1[(size_t)(base + i) * DD + j]), acc);
    atomicAdd(&g_h1[j], acc);
}

// ---------------------------------------------------------------------------
// K9: out = relu(h1 + b1) @ W2 + b2
// ---------------------------------------------------------------------------
__global__ void kout(const float* __restrict__ b1, const float* __restrict__ W2,
                     const float* __restrict__ b2, float* __restrict__ out) {
    int d = threadIdx.x;
    float v = fmaxf(g_h1[d] + b1[d], 0.f);
    float p = v * W2[d];
    #pragma unroll
    for (int o = 16; o; o >>= 1) p += __shfl_xor_sync(0xffffffffu, p, o);
    __shared__ float sp[4];
    if ((d & 31) == 0) sp[d >> 5] = p;
    __syncthreads();
    if (d == 0) out[0] = sp[0] + sp[1] + sp[2] + sp[3] + b2[0];
}

// ---------------------------------------------------------------------------
extern "C" void kernel_launch(void* const* d_in, const int* in_sizes, int n_in,
                              void* d_out, int out_size) {
    const float* x    = (const float*)d_in[0];
    const void*  ei   = d_in[1];
    const float* Win  = (const float*)d_in[2];
    const float* bin  = (const float*)d_in[3];
    const float* Wl   = (const float*)d_in[4];
    const float* bl   = (const float*)d_in[5];
    const float* Wr   = (const float*)d_in[6];
    const float* br   = (const float*)d_in[7];
    const float* att  = (const float*)d_in[8];
    const float* bias = (const float*)d_in[9];
    const float* W1   = (const float*)d_in[10];
    const float* b1   = (const float*)d_in[11];
    const float* W2   = (const float*)d_in[12];
    const float* b2   = (const float*)d_in[13];

    int Dd = in_sizes[8];          // 128
    int G  = in_sizes[3] / Dd;     // 5000
    int IN = in_sizes[0] / G;      // 64
    int E  = in_sizes[1] / 2;      // 240000
    int GD = G * Dd;
    (void)Dd; (void)n_in; (void)out_size;

    kz      <<<(G + 255) / 256, 256>>>(G);
    kflag   <<<(E + 255) / 256, 256>>>((const int*)ei, E);
    kconv   <<<(E + 255) / 256, 256>>>(ei, E);
    kscan   <<<1, 1024>>>(G);
    kscatter<<<(E + 255) / 256, 256>>>(E);
    kh      <<<G, DD>>>(x, Win, bin, IN);
    kxlxr   <<<(G + 7) / 8, DD>>>(Wl, bl, Wr, br, G);
    kgat    <<<G, DD>>>(att, bias);
    kmlp1   <<<(GD + 1023) / 1024, 256>>>(W1, GD);
    kout    <<<1, DD>>>(b1, W2, b2, (float*)d_out);
}

// round 3
// speedup vs baseline: 1.0026x; 1.0026x over previous
#include <cuda_runtime.h>
#include <math.h>

#define DD 128
static constexpr int MAXG = 5120;
static constexpr int MAXE = 262144;

__device__ __align__(16) float g_xl [MAXG * DD];
__device__ __align__(16) float g_xr [MAXG * DD];
__device__ __align__(16) float g_gat[MAXG * DD];
__device__ int   g_src[MAXE];
__device__ int   g_dst[MAXE];
__device__ int   g_es [MAXE];
__device__ int   g_off[MAXG + 1];
__device__ int   g_cur[MAXG];
__device__ int   g_deg[MAXG];
__device__ float g_h1 [DD];
__device__ int   g_flag = 0;   // never reset: input dtype is fixed across replays,
                               // so the OR-detection result is identical every run.

// ---------------------------------------------------------------------------
// K1: fused setup. Blocks [0,zB): zero deg/h1. Blocks [zB,..): dtype detect —
// if edge_index is int64 (values < G), every odd 32-bit word of row 0 is 0;
// if int32, odd words are random node ids -> OR is nonzero.
// ---------------------------------------------------------------------------
__global__ void ksetup(const int* __restrict__ w, int E, int G, int zB) {
    if ((int)blockIdx.x < zB) {
        int i = blockIdx.x * 256 + threadIdx.x;
        if (i < G)  g_deg[i] = 0;
        if (i < DD) g_h1[i]  = 0.f;
        return;
    }
    int i = (blockIdx.x - zB) * 256 + threadIdx.x;
    int v = 0;
    if (i < E) v = w[2 * i + 1];
    #pragma unroll
    for (int o = 16; o; o >>= 1) v |= __shfl_xor_sync(0xffffffffu, v, o);
    if ((threadIdx.x & 31) == 0 && v) atomicOr(&g_flag, 1);
}

// ---------------------------------------------------------------------------
// K2: fused. Blocks [0,convB): edge convert + degree histogram.
//     Blocks [convB,..): per-gene h = relu(x @ W_in + b_in) kept in SMEM,
//     immediately consumed by xl = h@W_l+b_l, xr = h@W_r+b_r (h never hits HBM).
//     8 genes per block, 256 threads = 2 genes in flight (half = tid>>7).
// ---------------------------------------------------------------------------
__global__ void kmain(const void* __restrict__ eidx, int E,
                      const float* __restrict__ x, const float* __restrict__ Win,
                      const float* __restrict__ bin, int IN,
                      const float* __restrict__ Wl, const float* __restrict__ bl,
                      const float* __restrict__ Wr, const float* __restrict__ br,
                      int G, int convB) {
    if ((int)blockIdx.x < convB) {
        int i = blockIdx.x * 256 + threadIdx.x;
        if (i >= E) return;
        int s, d;
        if (g_flag == 0) {
            const long long* p = (const long long*)eidx;
            s = (int)p[i]; d = (int)p[(size_t)E + i];
        } else {
            const int* p = (const int*)eidx;
            s = p[i]; d = p[E + i];
        }
        g_src[i] = s;
        g_dst[i] = d;
        atomicAdd(&g_deg[d], 1);
        return;
    }

    __shared__ float sh[8][DD];
    int b    = blockIdx.x - convB;
    int g0   = b * 8;
    int tid  = threadIdx.x;
    int d    = tid & 127;
    int half = tid >> 7;

    // h phase: halves process genes g0+2p+half, p=0..3
    for (int p = 0; p < 4; p++) {
        int g = g0 + 2 * p + half;
        float hv = 0.f;
        if (g < G) {
            float acc = bin[(size_t)g * DD + d];
            const float* w  = Win + (size_t)g * IN * DD + d;
            const float* xg = x + (size_t)g * IN;
            #pragma unroll 8
            for (int i = 0; i < IN; i++) acc = fmaf(xg[i], w[(size_t)i * DD], acc);
            hv = fmaxf(acc, 0.f);
        }
        sh[2 * p + half][d] = hv;
    }
    __syncthreads();

    // xl/xr phase: half handles rows {half, 2+half, 4+half, 6+half}
    float al[4], ar[4];
    float bld = bl[d], brd = br[d];
    #pragma unroll
    for (int r = 0; r < 4; r++) { al[r] = bld; ar[r] = brd; }
    for (int k = 0; k < DD; k++) {
        float wl = Wl[k * DD + d];
        float wr = Wr[k * DD + d];
        #pragma unroll
        for (int r = 0; r < 4; r++) {
            float hk = sh[2 * r + half][k];
            al[r] = fmaf(hk, wl, al[r]);
            ar[r] = fmaf(hk, wr, ar[r]);
        }
    }
    #pragma unroll
    for (int r = 0; r < 4; r++) {
        int g = g0 + 2 * r + half;
        if (g < G) {
            g_xl[(size_t)g * DD + d] = al[r];
            g_xr[(size_t)g * DD + d] = ar[r];
        }
    }
}

// ---------------------------------------------------------------------------
// K3: single-block scan, 5 elements/thread + warp-shuffle block scan (2 syncs)
// ---------------------------------------------------------------------------
__global__ void kscan(int G) {
    __shared__ int wsum[32];
    int tid = threadIdx.x, lane = tid & 31, wid = tid >> 5;
    int base = tid * 5;
    int v[5]; int s = 0;
    #pragma unroll
    for (int k = 0; k < 5; k++) {
        int i = base + k;
        v[k] = (i < G) ? g_deg[i] : 0;
        s += v[k];
    }
    int xinc = s;
    #pragma unroll
    for (int o = 1; o < 32; o <<= 1) {
        int t = __shfl_up_sync(0xffffffffu, xinc, o);
        if (lane >= o) xinc += t;
    }
    if (lane == 31) wsum[wid] = xinc;
    __syncthreads();
    if (wid == 0) {
        int y = wsum[lane];
        #pragma unroll
        for (int o = 1; o < 32; o <<= 1) {
            int t = __shfl_up_sync(0xffffffffu, y, o);
            if (lane >= o) y += t;
        }
        wsum[lane] = y;
    }
    __syncthreads();
    int run = xinc - s + (wid ? wsum[wid - 1] : 0);
    #pragma unroll
    for (int k = 0; k < 5; k++) {
        int i = base + k;
        if (i < G) {
            g_cur[i] = run;
            run += v[k];
            g_off[i + 1] = run;
        }
    }
    if (tid == 0) g_off[0] = 0;
}

// ---------------------------------------------------------------------------
// K4: scatter edges into CSR buckets
// ---------------------------------------------------------------------------
__global__ void kscatter(int E) {
    int i = blockIdx.x * blockDim.x + threadIdx.x;
    if (i >= E) return;
    int d   = g_dst[i];
    int pos = atomicAdd(&g_cur[d], 1);
    g_es[pos] = g_src[i];
}

// ---------------------------------------------------------------------------
// K5: GATv2 per destination node: 4 warps, online softmax, register-resident,
// smem merge. Warp 0 also handles the implicit self loop.
// ---------------------------------------------------------------------------
__global__ void kgat(const float* __restrict__ att, const float* __restrict__ bias) {
    int n = blockIdx.x;
    int tid = threadIdx.x, lane = tid & 31, wid = tid >> 5;

    const float4* xlv = (const float4*)g_xl;
    float4 att4 = ((const float4*)att)[lane];
    float4 xr4  = ((const float4*)(g_xr + (size_t)n * DD))[lane];

    int beg = g_off[n], end = g_off[n + 1];
    float  m = -INFINITY, z = 0.f;
    float4 acc = make_float4(0.f, 0.f, 0.f, 0.f);

    int  idx  = beg + wid;
    bool self = (wid == 0);
    while (self || idx < end) {
        int src;
        if (self) { src = n; self = false; }
        else      { src = g_es[idx]; idx += 4; }

        float4 xl4 = xlv[(size_t)src * (DD / 4) + lane];
        float tx = xl4.x + xr4.x, ty = xl4.y + xr4.y;
        float tz = xl4.z + xr4.z, tw = xl4.w + xr4.w;
        tx = tx >= 0.f ? tx : 0.2f * tx;
        ty = ty >= 0.f ? ty : 0.2f * ty;
        tz = tz >= 0.f ? tz : 0.2f * tz;
        tw = tw >= 0.f ? tw : 0.2f * tw;
        float p = att4.x * tx + att4.y * ty + att4.z * tz + att4.w * tw;
        #pragma unroll
        for (int o = 16; o; o >>= 1) p += __shfl_xor_sync(0xffffffffu, p, o);

        float mn = fmaxf(m, p);
        float sc = __expf(m - mn);
        float w  = __expf(p - mn);
        z     = z * sc + w;
        acc.x = acc.x * sc + w * xl4.x;
        acc.y = acc.y * sc + w * xl4.y;
        acc.z = acc.z * sc + w * xl4.z;
        acc.w = acc.w * sc + w * xl4.w;
        m = mn;
    }

    __shared__ float sm[4], szz[4];
    __shared__ float sacc[4][DD];
    if (lane == 0) { sm[wid] = m; szz[wid] = z; }
    sacc[wid][lane * 4 + 0] = acc.x;
    sacc[wid][lane * 4 + 1] = acc.y;
    sacc[wid][lane * 4 + 2] = acc.z;
    sacc[wid][lane * 4 + 3] = acc.w;
    __syncthreads();

    int d = tid;
    float M = fmaxf(fmaxf(sm[0], sm[1]), fmaxf(sm[2], sm[3]));
    float Z = 0.f, A = 0.f;
    #pragma unroll
    for (int w2 = 0; w2 < 4; w2++) {
        float s = __expf(sm[w2] - M);
        Z += szz[w2] * s;
        A += sacc[w2][d] * s;
    }
    float o = A / Z + bias[d];
    g_gat[(size_t)n * DD + d] = o >= 0.f ? o : 0.2f * o;
}

// ---------------------------------------------------------------------------
// K6: h1 += flat @ W1 — dominant 328MB stream, float4, warp-per-row.
// 8 warps/block, 1024 rows/block; lane's float4 covers cols 4l..4l+3.
// ---------------------------------------------------------------------------
__global__ void kmlp1(const float* __restrict__ W1, int GD) {
    __shared__ float  sf[1024];
    __shared__ float4 sacc[8][32];
    int tid = threadIdx.x, lane = tid & 31, wid = tid >> 5;
    int base = blockIdx.x * 1024;
    int lim  = min(1024, GD - base);
    for (int i = tid; i < lim; i += 256) sf[i] = g_gat[base + i];
    __syncthreads();

    const float4* W4 = (const float4*)W1;
    float4 acc = make_float4(0.f, 0.f, 0.f, 0.f);
    #pragma unroll 4
    for (int i = wid; i < lim; i += 8) {
        float  f = sf[i];
        float4 w = __ldg(&W4[(size_t)(base + i) * 32 + lane]);
        acc.x = fmaf(f, w.x, acc.x);
        acc.y = fmaf(f, w.y, acc.y);
        acc.z = fmaf(f, w.z, acc.z);
        acc.w = fmaf(f, w.w, acc.w);
    }
    sacc[wid][lane] = acc;
    __syncthreads();
    if (wid == 0) {
        float4 a = sacc[0][lane];
        #pragma unroll
        for (int w2 = 1; w2 < 8; w2++) {
            float4 b = sacc[w2][lane];
            a.x += b.x; a.y += b.y; a.z += b.z; a.w += b.w;
        }
        atomicAdd(&g_h1[4 * lane + 0], a.x);
        atomicAdd(&g_h1[4 * lane + 1], a.y);
        atomicAdd(&g_h1[4 * lane + 2], a.z);
        atomicAdd(&g_h1[4 * lane + 3], a.w);
    }
}

// ---------------------------------------------------------------------------
// K7: out = relu(h1 + b1) @ W2 + b2
// ---------------------------------------------------------------------------
__global__ void kout(const float* __restrict__ b1, const float* __restrict__ W2,
                     const float* __restrict__ b2, float* __restrict__ out) {
    int d = threadIdx.x;
    float v = fmaxf(g_h1[d] + b1[d], 0.f);
    float p = v * W2[d];
    #pragma unroll
    for (int o = 16; o; o >>= 1) p += __shfl_xor_sync(0xffffffffu, p, o);
    __shared__ float sp[4];
    if ((d & 31) == 0) sp[d >> 5] = p;
    __syncthreads();
    if (d == 0) out[0] = sp[0] + sp[1] + sp[2] + sp[3] + b2[0];
}

// ---------------------------------------------------------------------------
extern "C" void kernel_launch(void* const* d_in, const int* in_sizes, int n_in,
                              void* d_out, int out_size) {
    const float* x    = (const float*)d_in[0];
    const void*  ei   = d_in[1];
    const float* Win  = (const float*)d_in[2];
    const float* bin  = (const float*)d_in[3];
    const float* Wl   = (const float*)d_in[4];
    const float* bl   = (const float*)d_in[5];
    const float* Wr   = (const float*)d_in[6];
    const float* br   = (const float*)d_in[7];
    const float* att  = (const float*)d_in[8];
    const float* bias = (const float*)d_in[9];
    const float* W1   = (const float*)d_in[10];
    const float* b1   = (const float*)d_in[11];
    const float* W2   = (const float*)d_in[12];
    const float* b2   = (const float*)d_in[13];

    int Dd = in_sizes[8];          // 128
    int G  = in_sizes[3] / Dd;     // 5000
    int IN = in_sizes[0] / G;      // 64
    int E  = in_sizes[1] / 2;      // 240000
    int GD = G * Dd;
    (void)n_in; (void)out_size;

    int zB    = (G + 255) / 256;
    int fB    = (E + 255) / 256;
    int convB = (E + 255) / 256;
    int hxB   = (G + 7) / 8;

    ksetup  <<<zB + fB, 256>>>((const int*)ei, E, G, zB);
    kmain   <<<convB + hxB, 256>>>(ei, E, x, Win, bin, IN, Wl, bl, Wr, br, G, convB);
    kscan   <<<1, 1024>>>(G);
    kscatter<<<(E + 255) / 256, 256>>>(E);
    kgat    <<<G, DD>>>(att, bias);
    kmlp1   <<<(GD + 1023) / 1024, 256>>>(W1, GD);
    kout    <<<1, DD>>>(b1, W2, b2, (float*)d_out);
}

// round 4
// speedup vs baseline: 1.0603x; 1.0576x over previous
#include <cuda_runtime.h>
#include <math.h>

#define DD 128
static constexpr int MAXG = 5120;
static constexpr int MAXE = 262144;

__device__ __align__(16) float g_xl [MAXG * DD];
__device__ __align__(16) float g_xr [MAXG * DD];
__device__ __align__(16) float g_gat[MAXG * DD];
__device__ int   g_src[MAXE];
__device__ int   g_dst[MAXE];
__device__ int   g_es [MAXE];
__device__ int   g_off[MAXG + 1];
__device__ int   g_cur[MAXG];
__device__ int   g_deg[MAXG];
__device__ float g_h1 [DD];
__device__ int   g_flag = 0;   // never reset: input dtype fixed across replays,
                               // OR-detection result identical every run.

// ---------------------------------------------------------------------------
// K1: blocks [0,zB): zero deg/h1. Block zB: dtype detect on 256 samples —
// int64 node ids (<G) have zero odd words; int32 odd words are random ids.
// ---------------------------------------------------------------------------
__global__ void ksetup(const int* __restrict__ w, int E, int G, int zB) {
    if ((int)blockIdx.x < zB) {
        int i = blockIdx.x * 256 + threadIdx.x;
        if (i < G)  g_deg[i] = 0;
        if (i < DD) g_h1[i]  = 0.f;
        return;
    }
    int i = threadIdx.x;
    int v = 0;
    if (i < E) v = w[2 * i + 1];
    #pragma unroll
    for (int o = 16; o; o >>= 1) v |= __shfl_xor_sync(0xffffffffu, v, o);
    if ((threadIdx.x & 31) == 0 && v) atomicOr(&g_flag, 1);
}

// ---------------------------------------------------------------------------
// K2: edge convert + degree histogram
// ---------------------------------------------------------------------------
__global__ void kconv(const void* __restrict__ eidx, int E) {
    int i = blockIdx.x * 256 + threadIdx.x;
    if (i >= E) return;
    int s, d;
    if (g_flag == 0) {
        const long long* p = (const long long*)eidx;
        s = (int)p[i]; d = (int)p[(size_t)E + i];
    } else {
        const int* p = (const int*)eidx;
        s = p[i]; d = p[E + i];
    }
    g_src[i] = s;
    g_dst[i] = d;
    atomicAdd(&g_deg[d], 1);
}

// ---------------------------------------------------------------------------
// K3: single-block scan, 5 elems/thread + warp-shuffle block scan
// ---------------------------------------------------------------------------
__global__ void kscan(int G) {
    __shared__ int wsum[32];
    int tid = threadIdx.x, lane = tid & 31, wid = tid >> 5;
    int base = tid * 5;
    int v[5]; int s = 0;
    #pragma unroll
    for (int k = 0; k < 5; k++) {
        int i = base + k;
        v[k] = (i < G) ? g_deg[i] : 0;
        s += v[k];
    }
    int xinc = s;
    #pragma unroll
    for (int o = 1; o < 32; o <<= 1) {
        int t = __shfl_up_sync(0xffffffffu, xinc, o);
        if (lane >= o) xinc += t;
    }
    if (lane == 31) wsum[wid] = xinc;
    __syncthreads();
    if (wid == 0) {
        int y = wsum[lane];
        #pragma unroll
        for (int o = 1; o < 32; o <<= 1) {
            int t = __shfl_up_sync(0xffffffffu, y, o);
            if (lane >= o) y += t;
        }
        wsum[lane] = y;
    }
    __syncthreads();
    int run = xinc - s + (wid ? wsum[wid - 1] : 0);
    #pragma unroll
    for (int k = 0; k < 5; k++) {
        int i = base + k;
        if (i < G) {
            g_cur[i] = run;
            run += v[k];
            g_off[i + 1] = run;
        }
    }
    if (tid == 0) g_off[0] = 0;
}

// ---------------------------------------------------------------------------
// K4: scatter edges into CSR buckets
// ---------------------------------------------------------------------------
__global__ void kscatter(int E) {
    int i = blockIdx.x * blockDim.x + threadIdx.x;
    if (i >= E) return;
    int d   = g_dst[i];
    int pos = atomicAdd(&g_cur[d], 1);
    g_es[pos] = g_src[i];
}

// ---------------------------------------------------------------------------
// K5: fused h + xl/xr. 8 genes per 256-thread block.
// h phase: warp w handles gene g0+w with float4 lane loads (128B/thread
// in flight), h kept in registers -> smem. xl/xr phase: half 0 computes xl,
// half 1 computes xr for all 8 genes (8 accumulators, Wl/Wr read once/block).
// ---------------------------------------------------------------------------
__global__ void khx(const float* __restrict__ x, const float* __restrict__ Win,
                    const float* __restrict__ bin,
                    const float* __restrict__ Wl, const float* __restrict__ bl,
                    const float* __restrict__ Wr, const float* __restrict__ br,
                    int IN, int G) {
    __shared__ float sh[8][DD];
    int tid = threadIdx.x, lane = tid & 31, wid = tid >> 5;
    int g0 = blockIdx.x * 8;
    int g  = g0 + wid;

    float4 acc = make_float4(0.f, 0.f, 0.f, 0.f);
    if (g < G) {
        const float4* w4 = (const float4*)(Win + (size_t)g * IN * DD);
        const float*  xg = x + (size_t)g * IN;
        #pragma unroll 8
        for (int i = 0; i < IN; i++) {
            float  xi = xg[i];
            float4 w  = w4[(size_t)i * 32 + lane];
            acc.x = fmaf(xi, w.x, acc.x);
            acc.y = fmaf(xi, w.y, acc.y);
            acc.z = fmaf(xi, w.z, acc.z);
            acc.w = fmaf(xi, w.w, acc.w);
        }
        float4 bv = ((const float4*)(bin + (size_t)g * DD))[lane];
        acc.x = fmaxf(acc.x + bv.x, 0.f);
        acc.y = fmaxf(acc.y + bv.y, 0.f);
        acc.z = fmaxf(acc.z + bv.z, 0.f);
        acc.w = fmaxf(acc.w + bv.w, 0.f);
    }
    ((float4*)sh[wid])[lane] = acc;
    __syncthreads();

    int d    = tid & 127;
    int half = tid >> 7;
    const float* W   = half ? Wr : Wl;
    const float* bb  = half ? br : bl;
    float*       out = half ? g_xr : g_xl;
    float bd = bb[d];
    float a[8];
    #pragma unroll
    for (int r = 0; r < 8; r++) a[r] = bd;
    #pragma unroll 4
    for (int k = 0; k < DD; k++) {
        float w = W[k * DD + d];
        #pragma unroll
        for (int r = 0; r < 8; r++) a[r] = fmaf(sh[r][k], w, a[r]);
    }
    #pragma unroll
    for (int r = 0; r < 8; r++) {
        int gg = g0 + r;
        if (gg < G) out[(size_t)gg * DD + d] = a[r];
    }
}

// ---------------------------------------------------------------------------
// K6: GATv2 per destination node (chunked by n0): 4 warps, online softmax.
// ---------------------------------------------------------------------------
__global__ void kgat(const float* __restrict__ att, const float* __restrict__ bias,
                     int n0) {
    int n = blockIdx.x + n0;
    int tid = threadIdx.x, lane = tid & 31, wid = tid >> 5;

    const float4* xlv = (const float4*)g_xl;
    float4 att4 = ((const float4*)att)[lane];
    float4 xr4  = ((const float4*)(g_xr + (size_t)n * DD))[lane];

    int beg = g_off[n], end = g_off[n + 1];
    float  m = -INFINITY, z = 0.f;
    float4 acc = make_float4(0.f, 0.f, 0.f, 0.f);

    int  idx  = beg + wid;
    bool self = (wid == 0);
    while (self || idx < end) {
        int src;
        if (self) { src = n; self = false; }
        else      { src = g_es[idx]; idx += 4; }

        float4 xl4 = xlv[(size_t)src * (DD / 4) + lane];
        float tx = xl4.x + xr4.x, ty = xl4.y + xr4.y;
        float tz = xl4.z + xr4.z, tw = xl4.w + xr4.w;
        tx = tx >= 0.f ? tx : 0.2f * tx;
        ty = ty >= 0.f ? ty : 0.2f * ty;
        tz = tz >= 0.f ? tz : 0.2f * tz;
        tw = tw >= 0.f ? tw : 0.2f * tw;
        float p = att4.x * tx + att4.y * ty + att4.z * tz + att4.w * tw;
        #pragma unroll
        for (int o = 16; o; o >>= 1) p += __shfl_xor_sync(0xffffffffu, p, o);

        float mn = fmaxf(m, p);
        float sc = __expf(m - mn);
        float w  = __expf(p - mn);
        z     = z * sc + w;
        acc.x = acc.x * sc + w * xl4.x;
        acc.y = acc.y * sc + w * xl4.y;
        acc.z = acc.z * sc + w * xl4.z;
        acc.w = acc.w * sc + w * xl4.w;
        m = mn;
    }

    __shared__ float sm[4], szz[4];
    __shared__ float sacc[4][DD];
    if (lane == 0) { sm[wid] = m; szz[wid] = z; }
    sacc[wid][lane * 4 + 0] = acc.x;
    sacc[wid][lane * 4 + 1] = acc.y;
    sacc[wid][lane * 4 + 2] = acc.z;
    sacc[wid][lane * 4 + 3] = acc.w;
    __syncthreads();

    int d = tid;
    float M = fmaxf(fmaxf(sm[0], sm[1]), fmaxf(sm[2], sm[3]));
    float Z = 0.f, A = 0.f;
    #pragma unroll
    for (int w2 = 0; w2 < 4; w2++) {
        float s = __expf(sm[w2] - M);
        Z += szz[w2] * s;
        A += sacc[w2][d] * s;
    }
    float o = A / Z + bias[d];
    g_gat[(size_t)n * DD + d] = o >= 0.f ? o : 0.2f * o;
}

// ---------------------------------------------------------------------------
// K7: h1 += flat @ W1 — dominant 328MB stream, float4 + unroll 8.
// 8 warps, 1024 rows/block, chunked by blockOff for gat overlap.
// ---------------------------------------------------------------------------
__global__ void kmlp1(const float* __restrict__ W1, int blockOff, int GD) {
    __shared__ float  sf[1024];
    __shared__ float4 sacc[8][32];
    int tid = threadIdx.x, lane = tid & 31, wid = tid >> 5;
    int base = (blockIdx.x + blockOff) * 1024;
    int lim  = min(1024, GD - base);
    for (int i = tid; i < lim; i += 256) sf[i] = g_gat[base + i];
    __syncthreads();

    const float4* W4 = (const float4*)W1;
    float4 acc = make_float4(0.f, 0.f, 0.f, 0.f);
    #pragma unroll 8
    for (int i = wid; i < lim; i += 8) {
        float  f = sf[i];
        float4 w = __ldg(&W4[(size_t)(base + i) * 32 + lane]);
        acc.x = fmaf(f, w.x, acc.x);
        acc.y = fmaf(f, w.y, acc.y);
        acc.z = fmaf(f, w.z, acc.z);
        acc.w = fmaf(f, w.w, acc.w);
    }
    sacc[wid][lane] = acc;
    __syncthreads();
    if (wid == 0) {
        float4 a = sacc[0][lane];
        #pragma unroll
        for (int w2 = 1; w2 < 8; w2++) {
            float4 b = sacc[w2][lane];
            a.x += b.x; a.y += b.y; a.z += b.z; a.w += b.w;
        }
        atomicAdd(&g_h1[4 * lane + 0], a.x);
        atomicAdd(&g_h1[4 * lane + 1], a.y);
        atomicAdd(&g_h1[4 * lane + 2], a.z);
        atomicAdd(&g_h1[4 * lane + 3], a.w);
    }
}

// ---------------------------------------------------------------------------
// K8: out = relu(h1 + b1) @ W2 + b2
// ---------------------------------------------------------------------------
__global__ void kout(const float* __restrict__ b1, const float* __restrict__ W2,
                     const float* __restrict__ b2, float* __restrict__ out) {
    int d = threadIdx.x;
    float v = fmaxf(g_h1[d] + b1[d], 0.f);
    float p = v * W2[d];
    #pragma unroll
    for (int o = 16; o; o >>= 1) p += __shfl_xor_sync(0xffffffffu, p, o);
    __shared__ float sp[4];
    if ((d & 31) == 0) sp[d >> 5] = p;
    __syncthreads();
    if (d == 0) out[0] = sp[0] + sp[1] + sp[2] + sp[3] + b2[0];
}

// ---------------------------------------------------------------------------
extern "C" void kernel_launch(void* const* d_in, const int* in_sizes, int n_in,
                              void* d_out, int out_size) {
    const float* x    = (const float*)d_in[0];
    const void*  ei   = d_in[1];
    const float* Win  = (const float*)d_in[2];
    const float* bin  = (const float*)d_in[3];
    const float* Wl   = (const float*)d_in[4];
    const float* bl   = (const float*)d_in[5];
    const float* Wr   = (const float*)d_in[6];
    const float* br   = (const float*)d_in[7];
    const float* att  = (const float*)d_in[8];
    const float* bias = (const float*)d_in[9];
    const float* W1   = (const float*)d_in[10];
    const float* b1   = (const float*)d_in[11];
    const float* W2   = (const float*)d_in[12];
    const float* b2   = (const float*)d_in[13];

    int Dd = in_sizes[8];          // 128
    int G  = in_sizes[3] / Dd;     // 5000
    int IN = in_sizes[0] / G;      // 64
    int E  = in_sizes[1] / 2;      // 240000
    int GD = G * Dd;
    (void)n_in; (void)out_size;

    // one-time stream/event creation (host resources only; no device memory)
    static bool inited = false;
    static cudaStream_t sB;
    static cudaEvent_t evF, evE, evG0, evG1, evD;
    if (!inited) {
        cudaStreamCreateWithFlags(&sB, cudaStreamNonBlocking);
        cudaEventCreateWithFlags(&evF,  cudaEventDisableTiming);
        cudaEventCreateWithFlags(&evE,  cudaEventDisableTiming);
        cudaEventCreateWithFlags(&evG0, cudaEventDisableTiming);
        cudaEventCreateWithFlags(&evG1, cudaEventDisableTiming);
        cudaEventCreateWithFlags(&evD,  cudaEventDisableTiming);
        inited = true;
    }

    int zB = (G + 255) / 256;
    int eB = (E + 255) / 256;

    // gat/mlp1 chunk split aligned to 1024-row mlp1 blocks (8 genes/row-block)
    int totB = (GD + 1023) / 1024;        // 625
    int B0   = totB / 2 + (totB & 1) ? (totB + 1) / 2 : totB / 2;
    B0 = (totB + 1) / 2;                  // 313
    int C0   = B0 * 1024 / DD;            // genes covered by chunk 0 (2504)
    if (C0 > G) C0 = G;
    int B1   = totB - B0;

    // fork edge pipeline onto sB
    cudaEventRecord(evF, 0);
    cudaStreamWaitEvent(sB, evF, 0);
    ksetup  <<<zB + 1, 256, 0, sB>>>((const int*)ei, E, G, zB);
    kconv   <<<eB, 256, 0, sB>>>(ei, E);
    kscan   <<<1, 1024, 0, sB>>>(G);
    kscatter<<<eB, 256, 0, sB>>>(E);
    cudaEventRecord(evE, sB);

    // W_in stream on main stream, concurrent with edge pipeline
    khx<<<(G + 7) / 8, 256>>>(x, Win, bin, Wl, bl, Wr, br, IN, G);

    // join, then chunked gat
    cudaStreamWaitEvent(0, evE, 0);
    kgat<<<C0, DD>>>(att, bias, 0);
    cudaEventRecord(evG0, 0);
    if (G - C0 > 0) kgat<<<G - C0, DD>>>(att, bias, C0);
    cudaEventRecord(evG1, 0);

    // mlp1 chunks on sB, pipelined behind gat chunks
    cudaStreamWaitEvent(sB, evG0, 0);
    kmlp1<<<B0, 256, 0, sB>>>(W1, 0, GD);
    cudaStreamWaitEvent(sB, evG1, 0);
    if (B1 > 0) kmlp1<<<B1, 256, 0, sB>>>(W1, B0, GD);
    kout<<<1, DD, 0, sB>>>(b1, W2, b2, (float*)d_out);
    cudaEventRecord(evD, sB);
    cudaStreamWaitEvent(0, evD, 0);
}

// round 5
// speedup vs baseline: 1.3616x; 1.2842x over previous
#include <cuda_runtime.h>
#include <math.h>

#define DD 128
static constexpr int MAXG = 5120;
static constexpr int MAXE = 262144;
static constexpr int HR   = 8;       // h1 replication factor (atomic decontention)

__device__ __align__(16) float g_xl [MAXG * DD];
__device__ __align__(16) float g_xr [MAXG * DD];
__device__ int   g_src[MAXE];
__device__ int   g_dst[MAXE];
__device__ int   g_es [MAXE];
__device__ int   g_off[MAXG + 1];
__device__ int   g_cur[MAXG];
__device__ int   g_deg[MAXG];
__device__ float g_h1p[HR][DD];
__device__ int   g_flag = 0;   // never reset: input dtype fixed across replays,
                               // OR-detection result identical every run.

// ---------------------------------------------------------------------------
// K1: blocks [0,zB): zero deg + h1 replicas. Block zB: dtype detect on 256
// samples — int64 node ids (<G) have zero odd words; int32 odd words random.
// ---------------------------------------------------------------------------
__global__ void ksetup(const int* __restrict__ w, int E, int G, int zB) {
    if ((int)blockIdx.x < zB) {
        int i = blockIdx.x * 256 + threadIdx.x;
        if (i < G) g_deg[i] = 0;
        if (i < HR * DD) ((float*)g_h1p)[i] = 0.f;
        return;
    }
    int i = threadIdx.x;
    int v = 0;
    if (i < E) v = w[2 * i + 1];
    #pragma unroll
    for (int o = 16; o; o >>= 1) v |= __shfl_xor_sync(0xffffffffu, v, o);
    if ((threadIdx.x & 31) == 0 && v) atomicOr(&g_flag, 1);
}

// ---------------------------------------------------------------------------
// K2: edge convert + degree histogram
// ---------------------------------------------------------------------------
__global__ void kconv(const void* __restrict__ eidx, int E) {
    int i = blockIdx.x * 256 + threadIdx.x;
    if (i >= E) return;
    int s, d;
    if (g_flag == 0) {
        const long long* p = (const long long*)eidx;
        s = (int)p[i]; d = (int)p[(size_t)E + i];
    } else {
        const int* p = (const int*)eidx;
        s = p[i]; d = p[E + i];
    }
    g_src[i] = s;
    g_dst[i] = d;
    atomicAdd(&g_deg[d], 1);
}

// ---------------------------------------------------------------------------
// K3: single-block scan, 5 elems/thread + warp-shuffle block scan
// ---------------------------------------------------------------------------
__global__ void kscan(int G) {
    __shared__ int wsum[32];
    int tid = threadIdx.x, lane = tid & 31, wid = tid >> 5;
    int base = tid * 5;
    int v[5]; int s = 0;
    #pragma unroll
    for (int k = 0; k < 5; k++) {
        int i = base + k;
        v[k] = (i < G) ? g_deg[i] : 0;
        s += v[k];
    }
    int xinc = s;
    #pragma unroll
    for (int o = 1; o < 32; o <<= 1) {
        int t = __shfl_up_sync(0xffffffffu, xinc, o);
        if (lane >= o) xinc += t;
    }
    if (lane == 31) wsum[wid] = xinc;
    __syncthreads();
    if (wid == 0) {
        int y = wsum[lane];
        #pragma unroll
        for (int o = 1; o < 32; o <<= 1) {
            int t = __shfl_up_sync(0xffffffffu, y, o);
            if (lane >= o) y += t;
        }
        wsum[lane] = y;
    }
    __syncthreads();
    int run = xinc - s + (wid ? wsum[wid - 1] : 0);
    #pragma unroll
    for (int k = 0; k < 5; k++) {
        int i = base + k;
        if (i < G) {
            g_cur[i] = run;
            run += v[k];
            g_off[i + 1] = run;
        }
    }
    if (tid == 0) g_off[0] = 0;
}

// ---------------------------------------------------------------------------
// K4: scatter edges into CSR buckets
// ---------------------------------------------------------------------------
__global__ void kscatter(int E) {
    int i = blockIdx.x * blockDim.x + threadIdx.x;
    if (i >= E) return;
    int d   = g_dst[i];
    int pos = atomicAdd(&g_cur[d], 1);
    g_es[pos] = g_src[i];
}

// ---------------------------------------------------------------------------
// K5: fused h + xl/xr. 8 genes / 256-thread block; h lives only in smem.
// ---------------------------------------------------------------------------
__global__ void khx(const float* __restrict__ x, const float* __restrict__ Win,
                    const float* __restrict__ bin,
                    const float* __restrict__ Wl, const float* __restrict__ bl,
                    const float* __restrict__ Wr, const float* __restrict__ br,
                    int IN, int G) {
    __shared__ float sh[8][DD];
    int tid = threadIdx.x, lane = tid & 31, wid = tid >> 5;
    int g0 = blockIdx.x * 8;
    int g  = g0 + wid;

    float4 acc = make_float4(0.f, 0.f, 0.f, 0.f);
    if (g < G) {
        const float4* w4 = (const float4*)(Win + (size_t)g * IN * DD);
        const float*  xg = x + (size_t)g * IN;
        #pragma unroll 8
        for (int i = 0; i < IN; i++) {
            float  xi = xg[i];
            float4 w  = w4[(size_t)i * 32 + lane];
            acc.x = fmaf(xi, w.x, acc.x);
            acc.y = fmaf(xi, w.y, acc.y);
            acc.z = fmaf(xi, w.z, acc.z);
            acc.w = fmaf(xi, w.w, acc.w);
        }
        float4 bv = ((const float4*)(bin + (size_t)g * DD))[lane];
        acc.x = fmaxf(acc.x + bv.x, 0.f);
        acc.y = fmaxf(acc.y + bv.y, 0.f);
        acc.z = fmaxf(acc.z + bv.z, 0.f);
        acc.w = fmaxf(acc.w + bv.w, 0.f);
    }
    ((float4*)sh[wid])[lane] = acc;
    __syncthreads();

    int d    = tid & 127;
    int half = tid >> 7;
    const float* W   = half ? Wr : Wl;
    const float* bb  = half ? br : bl;
    float*       out = half ? g_xr : g_xl;
    float bd = bb[d];
    float a[8];
    #pragma unroll
    for (int r = 0; r < 8; r++) a[r] = bd;
    #pragma unroll 4
    for (int k = 0; k < DD; k++) {
        float w = W[k * DD + d];
        #pragma unroll
        for (int r = 0; r < 8; r++) a[r] = fmaf(sh[r][k], w, a[r]);
    }
    #pragma unroll
    for (int r = 0; r < 8; r++) {
        int gg = g0 + r;
        if (gg < G) out[(size_t)gg * DD + d] = a[r];
    }
}

// ---------------------------------------------------------------------------
// K6: FUSED GATv2 + MLP1 row-slice. Per destination node n:
//   phase A: 4-warp online-softmax gather -> gat row (leaky) in smem
//   phase B: stream this block's contiguous 64KB W1 slice (rows n*128..+127),
//            h1_partial[j] += gat[d] * W1[n*128+d, j]; block-reduce; 128
//            atomicAdds into 8-way replicated h1.
// While some blocks sit in gather latency, others stream W1 -> DRAM stays busy.
// ---------------------------------------------------------------------------
__global__ void kgm(const float* __restrict__ att, const float* __restrict__ bias,
                    const float* __restrict__ W1) {
    int n = blockIdx.x;
    int tid = threadIdx.x, lane = tid & 31, wid = tid >> 5;

    const float4* xlv = (const float4*)g_xl;
    float4 att4 = ((const float4*)att)[lane];
    float4 xr4  = ((const float4*)(g_xr + (size_t)n * DD))[lane];

    int beg = g_off[n], end = g_off[n + 1];
    float  m = -INFINITY, z = 0.f;
    float4 acc = make_float4(0.f, 0.f, 0.f, 0.f);

    int  idx  = beg + wid;
    bool self = (wid == 0);
    while (self || idx < end) {
        int src;
        if (self) { src = n; self = false; }
        else      { src = g_es[idx]; idx += 4; }

        float4 xl4 = xlv[(size_t)src * (DD / 4) + lane];
        float tx = xl4.x + xr4.x, ty = xl4.y + xr4.y;
        float tz = xl4.z + xr4.z, tw = xl4.w + xr4.w;
        tx = tx >= 0.f ? tx : 0.2f * tx;
        ty = ty >= 0.f ? ty : 0.2f * ty;
        tz = tz >= 0.f ? tz : 0.2f * tz;
        tw = tw >= 0.f ? tw : 0.2f * tw;
        float p = att4.x * tx + att4.y * ty + att4.z * tz + att4.w * tw;
        #pragma unroll
        for (int o = 16; o; o >>= 1) p += __shfl_xor_sync(0xffffffffu, p, o);

        float mn = fmaxf(m, p);
        float sc = __expf(m - mn);
        float w  = __expf(p - mn);
        z     = z * sc + w;
        acc.x = acc.x * sc + w * xl4.x;
        acc.y = acc.y * sc + w * xl4.y;
        acc.z = acc.z * sc + w * xl4.z;
        acc.w = acc.w * sc + w * xl4.w;
        m = mn;
    }

    __shared__ float sm[4], szz[4];
    __shared__ float sacc[4][DD];
    __shared__ float sgat[DD];
    if (lane == 0) { sm[wid] = m; szz[wid] = z; }
    sacc[wid][lane * 4 + 0] = acc.x;
    sacc[wid][lane * 4 + 1] = acc.y;
    sacc[wid][lane * 4 + 2] = acc.z;
    sacc[wid][lane * 4 + 3] = acc.w;
    __syncthreads();

    {
        int d = tid;
        float M = fmaxf(fmaxf(sm[0], sm[1]), fmaxf(sm[2], sm[3]));
        float Z = 0.f, A = 0.f;
        #pragma unroll
        for (int w2 = 0; w2 < 4; w2++) {
            float s = __expf(sm[w2] - M);
            Z += szz[w2] * s;
            A += sacc[w2][d] * s;
        }
        float o = A / Z + bias[d];
        sgat[d] = o >= 0.f ? o : 0.2f * o;
    }
    __syncthreads();

    // phase B: stream 64KB W1 slice. warp w handles rows w, 4+w, ..., 124+w.
    const float4* W4 = (const float4*)(W1 + (size_t)n * DD * DD);
    float4 h = make_float4(0.f, 0.f, 0.f, 0.f);
    #pragma unroll 8
    for (int r = wid; r < DD; r += 4) {
        float  f = sgat[r];
        float4 w = W4[(size_t)r * 32 + lane];
        h.x = fmaf(f, w.x, h.x);
        h.y = fmaf(f, w.y, h.y);
        h.z = fmaf(f, w.z, h.z);
        h.w = fmaf(f, w.w, h.w);
    }
    __shared__ float4 sred[4][32];
    sred[wid][lane] = h;
    __syncthreads();
    if (wid == 0) {
        float4 a = sred[0][lane];
        #pragma unroll
        for (int w2 = 1; w2 < 4; w2++) {
            float4 b = sred[w2][lane];
            a.x += b.x; a.y += b.y; a.z += b.z; a.w += b.w;
        }
        float* dst = g_h1p[n & (HR - 1)];
        atomicAdd(&dst[4 * lane + 0], a.x);
        atomicAdd(&dst[4 * lane + 1], a.y);
        atomicAdd(&dst[4 * lane + 2], a.z);
        atomicAdd(&dst[4 * lane + 3], a.w);
    }
}

// ---------------------------------------------------------------------------
// K7: out = relu(sum_replicas h1 + b1) @ W2 + b2
// ---------------------------------------------------------------------------
__global__ void kout(const float* __restrict__ b1, const float* __restrict__ W2,
                     const float* __restrict__ b2, float* __restrict__ out) {
    int d = threadIdx.x;
    float v = b1[d];
    #pragma unroll
    for (int r = 0; r < HR; r++) v += g_h1p[r][d];
    v = fmaxf(v, 0.f);
    float p = v * W2[d];
    #pragma unroll
    for (int o = 16; o; o >>= 1) p += __shfl_xor_sync(0xffffffffu, p, o);
    __shared__ float sp[4];
    if ((d & 31) == 0) sp[d >> 5] = p;
    __syncthreads();
    if (d == 0) out[0] = sp[0] + sp[1] + sp[2] + sp[3] + b2[0];
}

// ---------------------------------------------------------------------------
extern "C" void kernel_launch(void* const* d_in, const int* in_sizes, int n_in,
                              void* d_out, int out_size) {
    const float* x    = (const float*)d_in[0];
    const void*  ei   = d_in[1];
    const float* Win  = (const float*)d_in[2];
    const float* bin  = (const float*)d_in[3];
    const float* Wl   = (const float*)d_in[4];
    const float* bl   = (const float*)d_in[5];
    const float* Wr   = (const float*)d_in[6];
    const float* br   = (const float*)d_in[7];
    const float* att  = (const float*)d_in[8];
    const float* bias = (const float*)d_in[9];
    const float* W1   = (const float*)d_in[10];
    const float* b1   = (const float*)d_in[11];
    const float* W2   = (const float*)d_in[12];
    const float* b2   = (const float*)d_in[13];

    int Dd = in_sizes[8];          // 128
    int G  = in_sizes[3] / Dd;     // 5000
    int IN = in_sizes[0] / G;      // 64
    int E  = in_sizes[1] / 2;      // 240000
    (void)n_in; (void)out_size; (void)Dd;

    static bool inited = false;
    static cudaStream_t sB;
    static cudaEvent_t evF, evE;
    if (!inited) {
        cudaStreamCreateWithFlags(&sB, cudaStreamNonBlocking);
        cudaEventCreateWithFlags(&evF, cudaEventDisableTiming);
        cudaEventCreateWithFlags(&evE, cudaEventDisableTiming);
        inited = true;
    }

    int zB = (G + 255) / 256;
    int eB = (E + 255) / 256;

    // fork edge pipeline onto sB, concurrent with the W_in stream (khx)
    cudaEventRecord(evF, 0);
    cudaStreamWaitEvent(sB, evF, 0);
    ksetup  <<<zB + 1, 256, 0, sB>>>((const int*)ei, E, G, zB);
    kconv   <<<eB, 256, 0, sB>>>(ei, E);
    kscan   <<<1, 1024, 0, sB>>>(G);
    kscatter<<<eB, 256, 0, sB>>>(E);
    cudaEventRecord(evE, sB);

    khx<<<(G + 7) / 8, 256>>>(x, Win, bin, Wl, bl, Wr, br, IN, G);

    // join, then fused GAT + W1 stream, then output head
    cudaStreamWaitEvent(0, evE, 0);
    kgm <<<G, DD>>>(att, bias, W1);
    kout<<<1, DD>>>(b1, W2, b2, (float*)d_out);
}